// round 4
// baseline (speedup 1.0000x reference)
#include <cuda_runtime.h>

// Problem constants (fixed shapes)
#define HH 256
#define WW 256
#define NB 2
#define C4 256
#define CC 64
#define HW (HH*WW)

// ---------------- device scratch (allocation-free rule: __device__ globals) ----
__device__ float g_t0[NB*C4*HW];   // bn output (residual source)
__device__ float g_t1[NB*C4*HW];   // conv1 output
__device__ float g_t2[NB*C4*HW];   // resb output
__device__ float g_Q [NB*CC*HW];   // bq(resb(bn(cat_left)))
__device__ float g_K [NB*CC*HW];   // bs(resb(bn(cat_right)))
__device__ float g_scale[C4];
__device__ float g_shift[C4];

// ---------------- BN batch-stats (per channel over B,H,W) ---------------------
__global__ __launch_bounds__(256) void bn_stats_kernel(
    const float* __restrict__ in, const float* __restrict__ gamma,
    const float* __restrict__ beta, float* __restrict__ scale, float* __restrict__ shift)
{
    int ch = blockIdx.x, tid = threadIdx.x;
    float s = 0.f, s2 = 0.f;
    for (int b = 0; b < NB; b++) {
        const float* p = in + ((size_t)b*C4 + ch)*HW;
        for (int i = tid; i < HW; i += 256) { float v = p[i]; s += v; s2 += v*v; }
    }
    __shared__ float r1[256], r2[256];
    r1[tid] = s; r2[tid] = s2; __syncthreads();
    for (int o = 128; o > 0; o >>= 1) {
        if (tid < o) { r1[tid] += r1[tid+o]; r2[tid] += r2[tid+o]; }
        __syncthreads();
    }
    if (tid == 0) {
        const float invn = 1.f/(float)(NB*HW);
        float mean = r1[0]*invn;
        float var  = r2[0]*invn - mean*mean;
        float istd = 1.0f/sqrtf(var + 1e-5f);
        float sc = gamma[ch]*istd;
        scale[ch] = sc;
        shift[ch] = beta[ch] - sc*mean;
    }
}

// ---------------- BN apply (elementwise, float4) ------------------------------
__global__ __launch_bounds__(256) void bn_apply_kernel(
    const float4* __restrict__ in, const float* __restrict__ scale,
    const float* __restrict__ shift, float4* __restrict__ out)
{
    const int n4 = NB*C4*HW/4;
    for (int i = blockIdx.x*256 + threadIdx.x; i < n4; i += gridDim.x*256) {
        int ch = (i >> 14) & 255;            // (4*i >> 16) & 255
        float sc = scale[ch], sh = shift[ch];
        float4 v = in[i];
        v.x = v.x*sc + sh; v.y = v.y*sc + sh;
        v.z = v.z*sc + sh; v.w = v.w*sc + sh;
        out[i] = v;
    }
}

// ---------------- grouped 3x3 conv (groups=4, 256->256), pad=1 ----------------
// CTA: 32x8 pixel tile x 16 output channels. Thread: 4 oc x 4 px accumulators.
__global__ __launch_bounds__(256) void conv3x3_kernel(
    const float* __restrict__ in, const float* __restrict__ wgt,
    const float* __restrict__ bias, const float* __restrict__ res,
    float* __restrict__ out, int leaky)
{
    __shared__ float s_in[8][10][35];      // 8 ic x (10 rows x 34 cols used, stride 35)
    __shared__ float s_w[16][8][9];        // 16 oc x 8 ic x 9 taps
    const int tid = threadIdx.x;
    const int x0 = blockIdx.x * 32, y0 = blockIdx.y * 8;
    const int bz = blockIdx.z;
    const int b = bz >> 4, octile = bz & 15;
    const int oc0 = octile * 16;
    const int g   = oc0 >> 6;              // group of all 16 ocs
    const int qx  = tid & 7;               // x-quad (4 px each)
    const int ly  = (tid >> 3) & 7;        // row within tile
    const int qoc = tid >> 6;              // oc-quad (4 oc each)

    float acc[4][4];
    #pragma unroll
    for (int i = 0; i < 4; i++)
        #pragma unroll
        for (int j = 0; j < 4; j++) acc[i][j] = 0.f;

    for (int icb = 0; icb < 64; icb += 8) {
        __syncthreads();
        // load input tile 8 ic x 10 x 34 (zero-padded borders)
        for (int e = tid; e < 8*10*34; e += 256) {
            int icc = e / 340; int rem = e - icc*340;
            int ry = rem / 34; int rx = rem - ry*34;
            int gy = y0 - 1 + ry, gx = x0 - 1 + rx;
            float v = 0.f;
            if ((unsigned)gy < (unsigned)HH && (unsigned)gx < (unsigned)WW)
                v = in[(((size_t)b*C4 + g*64 + icb + icc)*HH + gy)*WW + gx];
            s_in[icc][ry][rx] = v;
        }
        // load weights 16 oc x 8 ic x 9
        for (int e = tid; e < 1152; e += 256) {
            int ocl = e / 72; int rem = e - ocl*72;
            int icc = rem / 9; int k = rem - icc*9;
            s_w[ocl][icc][k] = wgt[((size_t)(oc0 + ocl)*64 + icb + icc)*9 + k];
        }
        __syncthreads();
        #pragma unroll
        for (int icc = 0; icc < 8; icc++) {
            float v[3][6];
            #pragma unroll
            for (int ry = 0; ry < 3; ry++)
                #pragma unroll
                for (int cx = 0; cx < 6; cx++)
                    v[ry][cx] = s_in[icc][ly + ry][qx*4 + cx];
            #pragma unroll
            for (int ol = 0; ol < 4; ol++) {
                float w9[9];
                #pragma unroll
                for (int k = 0; k < 9; k++) w9[k] = s_w[qoc*4 + ol][icc][k];
                #pragma unroll
                for (int px = 0; px < 4; px++)
                    #pragma unroll
                    for (int ky = 0; ky < 3; ky++)
                        #pragma unroll
                        for (int kx = 0; kx < 3; kx++)
                            acc[ol][px] += v[ky][px + kx] * w9[ky*3 + kx];
            }
        }
    }
    // epilogue
    #pragma unroll
    for (int ol = 0; ol < 4; ol++) {
        int oc = oc0 + qoc*4 + ol;
        float bv = bias[oc];
        #pragma unroll
        for (int px = 0; px < 4; px++) {
            int y = y0 + ly, x = x0 + qx*4 + px;
            float val = acc[ol][px] + bv;
            if (leaky) val = val > 0.f ? val : 0.1f * val;
            size_t o = (((size_t)b*C4 + oc)*HH + y)*WW + x;
            if (res) val += res[o];
            out[o] = val;
        }
    }
}

// ---------------- grouped 1x1 conv (groups=4, 256->64) ------------------------
// CTA: 32 pixels (one row segment) x all 64 ocs. Thread: 8 ocs x 1 px.
__global__ __launch_bounds__(256) void conv1x1_kernel(
    const float* __restrict__ in, const float* __restrict__ wgt,
    const float* __restrict__ bias, float* __restrict__ out)
{
    __shared__ float s_in[C4][32];   // 32 KB
    __shared__ float s_w[CC][CC];    // 16 KB
    const int tid = threadIdx.x;
    const int b = blockIdx.z, y = blockIdx.y, x0 = blockIdx.x * 32;

    for (int e = tid; e < C4*32; e += 256) {
        int ch = e >> 5, px = e & 31;
        s_in[ch][px] = in[(((size_t)b*C4 + ch)*HH + y)*WW + x0 + px];
    }
    for (int e = tid; e < CC*CC; e += 256) s_w[e >> 6][e & 63] = wgt[e];
    __syncthreads();

    const int px = tid & 31;
    const int oc0 = (tid >> 5) * 8;   // 8 ocs, 8-aligned => single group (16-sized)
    const int g = oc0 >> 4;
    float acc[8];
    #pragma unroll
    for (int k = 0; k < 8; k++) acc[k] = 0.f;
    for (int ic = 0; ic < 64; ic++) {
        float v = s_in[g*64 + ic][px];
        #pragma unroll
        for (int k = 0; k < 8; k++) acc[k] += v * s_w[oc0 + k][ic];
    }
    #pragma unroll
    for (int k = 0; k < 8; k++)
        out[(((size_t)b*CC + oc0 + k)*HH + y)*WW + x0 + px] = acc[k] + bias[oc0 + k];
}

// ---------------- windowed parallax attention ---------------------------------
// One CTA per 8x8 window (p = hn idx, r = wn idx). 256 threads.
// Fp: properly-patchified feature. Fg: gather-source feature (scrambled patchify).
// dir=0 (r2l): col = max(j-d,0), mask = (x-d>=0). dir=1 (l2r): col = min(j+d,255), mask = (x+d<=255).
__global__ __launch_bounds__(256) void attn_kernel(
    const float* __restrict__ Fp, const float* __restrict__ Fg,
    const int* __restrict__ disp, const float* __restrict__ xg,
    const float* __restrict__ xb, float* __restrict__ out, int dir)
{
    __shared__ float sQ[64][65];
    __shared__ float sK[64][65];
    __shared__ int   scol[512];     // [q*64 + a]
    __shared__ float smean[8];

    const int tid = threadIdx.x;
    const int r = blockIdx.x, p = blockIdx.y, b = blockIdx.z;
    const int y0 = p*8, x0 = r*8;
    const int ioff = p >> 3;                   // i = 4a + ioff
    const int jb   = (p & 7)*32 + (r >> 3);    // j = jb + 4q
    const int chb  = (r & 7)*8;                // ch' = chb + s

    // proper patch: sQ[p1][a] = Fp[b][a][y0 + p1/8][x0 + p1%8]
    for (int e = tid; e < 4096; e += 256) {
        int a = e >> 6, p1 = e & 63;
        sQ[p1][a] = Fp[(((size_t)b*CC + a)*HH + y0 + (p1 >> 3))*WW + x0 + (p1 & 7)];
    }
    // gather column indices (512 distinct (i,j) pairs)
    for (int e = tid; e < 512; e += 256) {
        int q = e >> 6, a = e & 63;
        int i = 4*a + ioff, j = jb + 4*q;
        int d = disp[((size_t)b*HH + i)*WW + j];
        scol[e] = dir ? min(j + d, WW-1) : max(j - d, 0);
    }
    __syncthreads();
    // scrambled-patchify gather: sK[p2=(q,s)][a] = Fg[b][chb+s][4a+ioff][col(q,a)]
    for (int e = tid; e < 4096; e += 256) {
        int p2 = e >> 6, a = e & 63;
        int q = p2 >> 3, s = p2 & 7;
        sK[p2][a] = Fg[(((size_t)b*CC + chb + s)*HH + 4*a + ioff)*WW + scol[q*64 + a]];
    }
    __syncthreads();
    // per-q mean over (s,a) = 512 values; one warp per q
    {
        int wid = tid >> 5, lane = tid & 31;
        float sum = 0.f;
        #pragma unroll
        for (int k = 0; k < 16; k++) {
            int f = lane + 32*k;
            sum += sK[wid*8 + (f >> 6)][f & 63];
        }
        #pragma unroll
        for (int o = 16; o; o >>= 1) sum += __shfl_xor_sync(0xffffffffu, sum, o);
        if (lane == 0) smean[wid] = sum * (1.f/512.f);
    }
    __syncthreads();
    for (int e = tid; e < 4096; e += 256)
        sK[e >> 6][e & 63] -= smean[e >> 9];   // (e>>6)>>3 = q
    __syncthreads();

    // matmul1: S[p1][p2] = sum_a sQ[p1][a]*sK[p2][a]; thread owns row p1, quarter c4
    const int p1 = tid >> 2, c4 = tid & 3;
    float acc[16];
    #pragma unroll
    for (int k = 0; k < 16; k++) acc[k] = 0.f;
    for (int a = 0; a < 64; a++) {
        float qv = sQ[p1][a];
        #pragma unroll
        for (int k = 0; k < 16; k++) acc[k] += qv * sK[c4 + 4*k][a];
    }
    // softmax across the 4-thread quad (rows of 64)
    float m = acc[0];
    #pragma unroll
    for (int k = 1; k < 16; k++) m = fmaxf(m, acc[k]);
    m = fmaxf(m, __shfl_xor_sync(0xffffffffu, m, 1));
    m = fmaxf(m, __shfl_xor_sync(0xffffffffu, m, 2));
    float ssum = 0.f;
    #pragma unroll
    for (int k = 0; k < 16; k++) { acc[k] = expf(acc[k] - m); ssum += acc[k]; }
    ssum += __shfl_xor_sync(0xffffffffu, ssum, 1);
    ssum += __shfl_xor_sync(0xffffffffu, ssum, 2);
    float inv = 1.f/ssum;
    __syncthreads();                     // all matmul1 reads of sQ/sK done
    #pragma unroll
    for (int k = 0; k < 16; k++) sQ[p1][c4 + 4*k] = acc[k]*inv;   // probs -> sQ
    // load gathered x into sK (same cols)
    for (int e = tid; e < 4096; e += 256) {
        int p2 = e >> 6, a = e & 63;
        int q = p2 >> 3, s = p2 & 7;
        sK[p2][a] = xg[(((size_t)b*CC + chb + s)*HH + 4*a + ioff)*WW + scol[q*64 + a]];
    }
    __syncthreads();
    // matmul2: Out[p1][a] = sum_p2 probs[p1][p2]*X[p2][a]
    float o16[16];
    #pragma unroll
    for (int k = 0; k < 16; k++) o16[k] = 0.f;
    for (int p2 = 0; p2 < 64; p2++) {
        float mv = sQ[p1][p2];
        #pragma unroll
        for (int k = 0; k < 16; k++) o16[k] += mv * sK[p2][c4 + 4*k];
    }
    __syncthreads();
    #pragma unroll
    for (int k = 0; k < 16; k++) sK[p1][c4 + 4*k] = o16[k];       // Out -> sK
    __syncthreads();
    // epilogue: out[b][a][y][x] = xb + Out*mask
    for (int e = tid; e < 4096; e += 256) {
        int a = e >> 6, pe = e & 63;
        int y = y0 + (pe >> 3), x = x0 + (pe & 7);
        int d = disp[((size_t)b*HH + y)*WW + x];
        bool ok = dir ? (x + d <= WW-1) : (x - d >= 0);
        size_t o = (((size_t)b*CC + a)*HH + y)*WW + x;
        out[o] = xb[o] + (ok ? sK[pe][a] : 0.f);
    }
}

// ---------------- launch -------------------------------------------------------
extern "C" void kernel_launch(void* const* d_in, const int* in_sizes, int n_in,
                              void* d_out, int out_size)
{
    const float* x_left  = (const float*)d_in[0];
    const float* x_right = (const float*)d_in[1];
    const float* cat_l   = (const float*)d_in[2];
    const float* cat_r   = (const float*)d_in[3];
    const int*   d_l     = (const int*)d_in[4];
    const int*   d_r     = (const int*)d_in[5];
    const float* gamma   = (const float*)d_in[6];
    const float* beta    = (const float*)d_in[7];
    const float* rw1     = (const float*)d_in[8];
    const float* rb1     = (const float*)d_in[9];
    const float* rw2     = (const float*)d_in[10];
    const float* rb2     = (const float*)d_in[11];
    const float* bqw     = (const float*)d_in[12];
    const float* bqb     = (const float*)d_in[13];
    const float* bsw     = (const float*)d_in[14];
    const float* bsb     = (const float*)d_in[15];

    float* out_left  = (float*)d_out;
    float* out_right = out_left + (size_t)NB*CC*HW;

    float *t0, *t1, *t2, *Qb, *Kb, *sc, *sh;
    cudaGetSymbolAddress((void**)&t0, g_t0);
    cudaGetSymbolAddress((void**)&t1, g_t1);
    cudaGetSymbolAddress((void**)&t2, g_t2);
    cudaGetSymbolAddress((void**)&Qb, g_Q);
    cudaGetSymbolAddress((void**)&Kb, g_K);
    cudaGetSymbolAddress((void**)&sc, g_scale);
    cudaGetSymbolAddress((void**)&sh, g_shift);

    dim3 cgrid(8, 32, 32);         // conv3x3: xtiles, ytiles, b*16 octiles
    dim3 pgrid(8, 256, 2);         // conv1x1: xblocks, rows, b
    dim3 agrid(32, 32, 2);         // attn: wn, hn, b

    // ---- LEFT branch -> Q ----
    bn_stats_kernel<<<256, 256>>>(cat_l, gamma, beta, sc, sh);
    bn_apply_kernel<<<4096, 256>>>((const float4*)cat_l, sc, sh, (float4*)t0);
    conv3x3_kernel<<<cgrid, 256>>>(t0, rw1, rb1, nullptr, t1, 1);
    conv3x3_kernel<<<cgrid, 256>>>(t1, rw2, rb2, t0, t2, 0);
    conv1x1_kernel<<<pgrid, 256>>>(t2, bqw, bqb, Qb);

    // ---- RIGHT branch -> K ----
    bn_stats_kernel<<<256, 256>>>(cat_r, gamma, beta, sc, sh);
    bn_apply_kernel<<<4096, 256>>>((const float4*)cat_r, sc, sh, (float4*)t0);
    conv3x3_kernel<<<cgrid, 256>>>(t0, rw1, rb1, nullptr, t1, 1);
    conv3x3_kernel<<<cgrid, 256>>>(t1, rw2, rb2, t0, t2, 0);
    conv1x1_kernel<<<pgrid, 256>>>(t2, bsw, bsb, Kb);

    // ---- attention: r2l -> out_left, l2r -> out_right ----
    attn_kernel<<<agrid, 256>>>(Qb, Kb, d_l, x_right, x_left,  out_left,  0);
    attn_kernel<<<agrid, 256>>>(Kb, Qb, d_r, x_left,  x_right, out_right, 1);
}

// round 8
// speedup vs baseline: 1.0260x; 1.0260x over previous
#include <cuda_runtime.h>

// Problem constants (fixed shapes)
#define HH 256
#define WW 256
#define NB 2
#define C4 256
#define CC 64
#define HW (HH*WW)

// ---------------- device scratch (allocation-free rule: __device__ globals) ----
__device__ float g_t1[NB*C4*HW];   // conv1 output
__device__ float g_t2[NB*C4*HW];   // resb output
__device__ float g_Q [NB*CC*HW];   // bq(resb(bn(cat_left)))
__device__ float g_K [NB*CC*HW];   // bs(resb(bn(cat_right)))
__device__ float g_scale[C4];
__device__ float g_shift[C4];

// ---------------- BN batch-stats (per channel over B,H,W) ---------------------
__global__ __launch_bounds__(256) void bn_stats_kernel(
    const float* __restrict__ in, const float* __restrict__ gamma,
    const float* __restrict__ beta, float* __restrict__ scale, float* __restrict__ shift)
{
    int ch = blockIdx.x, tid = threadIdx.x;
    float s = 0.f, s2 = 0.f;
    for (int b = 0; b < NB; b++) {
        const float4* p = (const float4*)(in + ((size_t)b*C4 + ch)*HW);
        for (int i = tid; i < HW/4; i += 256) {
            float4 v = p[i];
            s  += v.x + v.y + v.z + v.w;
            s2 += v.x*v.x + v.y*v.y + v.z*v.z + v.w*v.w;
        }
    }
    __shared__ float r1[256], r2[256];
    r1[tid] = s; r2[tid] = s2; __syncthreads();
    for (int o = 128; o > 0; o >>= 1) {
        if (tid < o) { r1[tid] += r1[tid+o]; r2[tid] += r2[tid+o]; }
        __syncthreads();
    }
    if (tid == 0) {
        const float invn = 1.f/(float)(NB*HW);
        float mean = r1[0]*invn;
        float var  = r2[0]*invn - mean*mean;
        float istd = 1.0f/sqrtf(var + 1e-5f);
        float sc = gamma[ch]*istd;
        scale[ch] = sc;
        shift[ch] = beta[ch] - sc*mean;
    }
}

// ---------------- grouped 3x3 conv (groups=4, 256->256), pad=1 ----------------
// CTA: 32x16 pixel tile x 16 output channels. Thread: 4 oc x 8 px accumulators.
// bn_in: apply per-channel affine (scale/shift) to the INPUT on load (zero padding
//        stays zero -- matches pad(bn(x))).
// resbase: if non-null, add resbase*scale[oc]+shift[oc] in the epilogue (bn residual).
__global__ __launch_bounds__(256, 2) void conv3x3_kernel(
    const float* __restrict__ in, const float* __restrict__ wgt,
    const float* __restrict__ bias, const float* __restrict__ resbase,
    const float* __restrict__ bnsc, const float* __restrict__ bnsh,
    float* __restrict__ out, int bn_in, int leaky)
{
    __shared__ float s_in[8][18][36];      // 8 ic x 18 rows x 34 cols used (stride 36, 16B-aligned rows)
    __shared__ float s_w[16][8][12];       // 16 oc x 8 ic x 9 taps (padded to 12)
    const int tid = threadIdx.x;
    const int x0 = blockIdx.x * 32, y0 = blockIdx.y * 16;
    const int bz = blockIdx.z;
    const int b = bz >> 4, octile = bz & 15;
    const int oc0 = octile * 16;
    const int g   = oc0 >> 6;              // group of all 16 ocs
    const int qx  = tid & 3;               // x-quad (8 px each)
    const int ly  = (tid >> 2) & 15;       // row within tile
    const int qoc = tid >> 6;              // oc-quad (4 oc each)

    float acc[4][8];
    #pragma unroll
    for (int i = 0; i < 4; i++)
        #pragma unroll
        for (int j = 0; j < 8; j++) acc[i][j] = 0.f;

    for (int icb = 0; icb < 64; icb += 8) {
        __syncthreads();
        // load input tile 8 ic x 18 x 34 (zero-padded borders), optional BN affine
        for (int e = tid; e < 8*18*34; e += 256) {
            int icc = e / 612; int rem = e - icc*612;
            int ry = rem / 34; int rx = rem - ry*34;
            int gy = y0 - 1 + ry, gx = x0 - 1 + rx;
            int chIn = g*64 + icb + icc;
            float v = 0.f;
            if ((unsigned)gy < (unsigned)HH && (unsigned)gx < (unsigned)WW) {
                v = in[(((size_t)b*C4 + chIn)*HH + gy)*WW + gx];
                if (bn_in) v = v * bnsc[chIn] + bnsh[chIn];
            }
            s_in[icc][ry][rx] = v;
        }
        // load weights 16 oc x 8 ic x 9 (stride 12)
        for (int e = tid; e < 1152; e += 256) {
            int ocl = e / 72; int rem = e - ocl*72;
            int icc = rem / 9; int k = rem - icc*9;
            s_w[ocl][icc][k] = wgt[((size_t)(oc0 + ocl)*64 + icb + icc)*9 + k];
        }
        __syncthreads();
        #pragma unroll
        for (int icc = 0; icc < 8; icc++) {
            float vv[3][12];
            #pragma unroll
            for (int ry = 0; ry < 3; ry++) {
                const float* row = &s_in[icc][ly + ry][qx*8];
                *(float4*)&vv[ry][0] = *(const float4*)&row[0];
                *(float4*)&vv[ry][4] = *(const float4*)&row[4];
                *(float4*)&vv[ry][8] = *(const float4*)&row[8];
            }
            #pragma unroll
            for (int ol = 0; ol < 4; ol++) {
                const float* wrow = &s_w[qoc*4 + ol][icc][0];
                float4 w0 = *(const float4*)&wrow[0];
                float4 w4 = *(const float4*)&wrow[4];
                float4 w8 = *(const float4*)&wrow[8];
                float w9[9] = {w0.x, w0.y, w0.z, w0.w, w4.x, w4.y, w4.z, w4.w, w8.x};
                #pragma unroll
                for (int px = 0; px < 8; px++)
                    #pragma unroll
                    for (int ky = 0; ky < 3; ky++)
                        #pragma unroll
                        for (int kx = 0; kx < 3; kx++)
                            acc[ol][px] += vv[ky][px + kx] * w9[ky*3 + kx];
            }
        }
    }
    // epilogue (vectorized stores; optional BN-affine residual, optional leaky)
    const int y = y0 + ly, xb8 = x0 + qx*8;
    #pragma unroll
    for (int ol = 0; ol < 4; ol++) {
        int oc = oc0 + qoc*4 + ol;
        float bv = bias[oc];
        float o8[8];
        #pragma unroll
        for (int px = 0; px < 8; px++) {
            float val = acc[ol][px] + bv;
            if (leaky) val = val > 0.f ? val : 0.1f * val;
            o8[px] = val;
        }
        size_t o = (((size_t)b*C4 + oc)*HH + y)*WW + xb8;
        if (resbase) {
            float rsc = bnsc[oc], rsh = bnsh[oc];
            float4 r0 = *(const float4*)&resbase[o];
            float4 r1 = *(const float4*)&resbase[o + 4];
            o8[0] += r0.x*rsc + rsh; o8[1] += r0.y*rsc + rsh;
            o8[2] += r0.z*rsc + rsh; o8[3] += r0.w*rsc + rsh;
            o8[4] += r1.x*rsc + rsh; o8[5] += r1.y*rsc + rsh;
            o8[6] += r1.z*rsc + rsh; o8[7] += r1.w*rsc + rsh;
        }
        *(float4*)&out[o]     = make_float4(o8[0], o8[1], o8[2], o8[3]);
        *(float4*)&out[o + 4] = make_float4(o8[4], o8[5], o8[6], o8[7]);
    }
}

// ---------------- grouped 1x1 conv (groups=4, 256->64) ------------------------
__global__ __launch_bounds__(256) void conv1x1_kernel(
    const float* __restrict__ in, const float* __restrict__ wgt,
    const float* __restrict__ bias, float* __restrict__ out)
{
    __shared__ float s_in[C4][32];   // 32 KB
    __shared__ float s_w[CC][CC];    // 16 KB
    const int tid = threadIdx.x;
    const int b = blockIdx.z, y = blockIdx.y, x0 = blockIdx.x * 32;

    for (int e = tid; e < C4*32; e += 256) {
        int ch = e >> 5, px = e & 31;
        s_in[ch][px] = in[(((size_t)b*C4 + ch)*HH + y)*WW + x0 + px];
    }
    for (int e = tid; e < CC*CC; e += 256) s_w[e >> 6][e & 63] = wgt[e];
    __syncthreads();

    const int px = tid & 31;
    const int oc0 = (tid >> 5) * 8;
    const int g = oc0 >> 4;
    float acc[8];
    #pragma unroll
    for (int k = 0; k < 8; k++) acc[k] = 0.f;
    for (int ic = 0; ic < 64; ic++) {
        float v = s_in[g*64 + ic][px];
        #pragma unroll
        for (int k = 0; k < 8; k++) acc[k] += v * s_w[oc0 + k][ic];
    }
    #pragma unroll
    for (int k = 0; k < 8; k++)
        out[(((size_t)b*CC + oc0 + k)*HH + y)*WW + x0 + px] = acc[k] + bias[oc0 + k];
}

// ---------------- windowed parallax attention ---------------------------------
// One CTA per 8x8 window (p = hn idx, r = wn idx). 256 threads.
__global__ __launch_bounds__(256) void attn_kernel(
    const float* __restrict__ Fp, const float* __restrict__ Fg,
    const int* __restrict__ disp, const float* __restrict__ xg,
    const float* __restrict__ xb, float* __restrict__ out, int dir)
{
    __shared__ float sQ[64][65];
    __shared__ float sK[64][65];
    __shared__ int   scol[512];     // [q*64 + a]
    __shared__ float smean[8];

    const int tid = threadIdx.x;
    const int r = blockIdx.x, p = blockIdx.y, b = blockIdx.z;
    const int y0 = p*8, x0 = r*8;
    const int ioff = p >> 3;                   // i = 4a + ioff
    const int jb   = (p & 7)*32 + (r >> 3);    // j = jb + 4q
    const int chb  = (r & 7)*8;                // ch' = chb + s

    for (int e = tid; e < 4096; e += 256) {
        int a = e >> 6, p1 = e & 63;
        sQ[p1][a] = Fp[(((size_t)b*CC + a)*HH + y0 + (p1 >> 3))*WW + x0 + (p1 & 7)];
    }
    for (int e = tid; e < 512; e += 256) {
        int q = e >> 6, a = e & 63;
        int i = 4*a + ioff, j = jb + 4*q;
        int d = disp[((size_t)b*HH + i)*WW + j];
        scol[e] = dir ? min(j + d, WW-1) : max(j - d, 0);
    }
    __syncthreads();
    for (int e = tid; e < 4096; e += 256) {
        int p2 = e >> 6, a = e & 63;
        int q = p2 >> 3, s = p2 & 7;
        sK[p2][a] = Fg[(((size_t)b*CC + chb + s)*HH + 4*a + ioff)*WW + scol[q*64 + a]];
    }
    __syncthreads();
    {
        int wid = tid >> 5, lane = tid & 31;
        float sum = 0.f;
        #pragma unroll
        for (int k = 0; k < 16; k++) {
            int f = lane + 32*k;
            sum += sK[wid*8 + (f >> 6)][f & 63];
        }
        #pragma unroll
        for (int o = 16; o; o >>= 1) sum += __shfl_xor_sync(0xffffffffu, sum, o);
        if (lane == 0) smean[wid] = sum * (1.f/512.f);
    }
    __syncthreads();
    for (int e = tid; e < 4096; e += 256)
        sK[e >> 6][e & 63] -= smean[e >> 9];
    __syncthreads();

    const int p1 = tid >> 2, c4 = tid & 3;
    float acc[16];
    #pragma unroll
    for (int k = 0; k < 16; k++) acc[k] = 0.f;
    for (int a = 0; a < 64; a++) {
        float qv = sQ[p1][a];
        #pragma unroll
        for (int k = 0; k < 16; k++) acc[k] += qv * sK[c4 + 4*k][a];
    }
    float m = acc[0];
    #pragma unroll
    for (int k = 1; k < 16; k++) m = fmaxf(m, acc[k]);
    m = fmaxf(m, __shfl_xor_sync(0xffffffffu, m, 1));
    m = fmaxf(m, __shfl_xor_sync(0xffffffffu, m, 2));
    float ssum = 0.f;
    #pragma unroll
    for (int k = 0; k < 16; k++) { acc[k] = expf(acc[k] - m); ssum += acc[k]; }
    ssum += __shfl_xor_sync(0xffffffffu, ssum, 1);
    ssum += __shfl_xor_sync(0xffffffffu, ssum, 2);
    float inv = 1.f/ssum;
    __syncthreads();
    #pragma unroll
    for (int k = 0; k < 16; k++) sQ[p1][c4 + 4*k] = acc[k]*inv;
    for (int e = tid; e < 4096; e += 256) {
        int p2 = e >> 6, a = e & 63;
        int q = p2 >> 3, s = p2 & 7;
        sK[p2][a] = xg[(((size_t)b*CC + chb + s)*HH + 4*a + ioff)*WW + scol[q*64 + a]];
    }
    __syncthreads();
    float o16[16];
    #pragma unroll
    for (int k = 0; k < 16; k++) o16[k] = 0.f;
    for (int p2 = 0; p2 < 64; p2++) {
        float mv = sQ[p1][p2];
        #pragma unroll
        for (int k = 0; k < 16; k++) o16[k] += mv * sK[p2][c4 + 4*k];
    }
    __syncthreads();
    #pragma unroll
    for (int k = 0; k < 16; k++) sK[p1][c4 + 4*k] = o16[k];
    __syncthreads();
    for (int e = tid; e < 4096; e += 256) {
        int a = e >> 6, pe = e & 63;
        int y = y0 + (pe >> 3), x = x0 + (pe & 7);
        int d = disp[((size_t)b*HH + y)*WW + x];
        bool ok = dir ? (x + d <= WW-1) : (x - d >= 0);
        size_t o = (((size_t)b*CC + a)*HH + y)*WW + x;
        out[o] = xb[o] + (ok ? sK[pe][a] : 0.f);
    }
}

// ---------------- launch -------------------------------------------------------
extern "C" void kernel_launch(void* const* d_in, const int* in_sizes, int n_in,
                              void* d_out, int out_size)
{
    const float* x_left  = (const float*)d_in[0];
    const float* x_right = (const float*)d_in[1];
    const float* cat_l   = (const float*)d_in[2];
    const float* cat_r   = (const float*)d_in[3];
    const int*   d_l     = (const int*)d_in[4];
    const int*   d_r     = (const int*)d_in[5];
    const float* gamma   = (const float*)d_in[6];
    const float* beta    = (const float*)d_in[7];
    const float* rw1     = (const float*)d_in[8];
    const float* rb1     = (const float*)d_in[9];
    const float* rw2     = (const float*)d_in[10];
    const float* rb2     = (const float*)d_in[11];
    const float* bqw     = (const float*)d_in[12];
    const float* bqb     = (const float*)d_in[13];
    const float* bsw     = (const float*)d_in[14];
    const float* bsb     = (const float*)d_in[15];

    float* out_left  = (float*)d_out;
    float* out_right = out_left + (size_t)NB*CC*HW;

    float *t1, *t2, *Qb, *Kb, *sc, *sh;
    cudaGetSymbolAddress((void**)&t1, g_t1);
    cudaGetSymbolAddress((void**)&t2, g_t2);
    cudaGetSymbolAddress((void**)&Qb, g_Q);
    cudaGetSymbolAddress((void**)&Kb, g_K);
    cudaGetSymbolAddress((void**)&sc, g_scale);
    cudaGetSymbolAddress((void**)&sh, g_shift);

    dim3 cgrid(8, 16, 32);         // conv3x3: xtiles(32), ytiles(16), b*16 octiles
    dim3 pgrid(8, 256, 2);         // conv1x1: xblocks, rows, b
    dim3 agrid(32, 32, 2);         // attn: wn, hn, b

    // ---- LEFT branch -> Q ----
    bn_stats_kernel<<<256, 256>>>(cat_l, gamma, beta, sc, sh);
    conv3x3_kernel<<<cgrid, 256>>>(cat_l, rw1, rb1, nullptr, sc, sh, t1, 1, 1);
    conv3x3_kernel<<<cgrid, 256>>>(t1,    rw2, rb2, cat_l,   sc, sh, t2, 0, 0);
    conv1x1_kernel<<<pgrid, 256>>>(t2, bqw, bqb, Qb);

    // ---- RIGHT branch -> K ----
    bn_stats_kernel<<<256, 256>>>(cat_r, gamma, beta, sc, sh);
    conv3x3_kernel<<<cgrid, 256>>>(cat_r, rw1, rb1, nullptr, sc, sh, t1, 1, 1);
    conv3x3_kernel<<<cgrid, 256>>>(t1,    rw2, rb2, cat_r,   sc, sh, t2, 0, 0);
    conv1x1_kernel<<<pgrid, 256>>>(t2, bsw, bsb, Kb);

    // ---- attention: r2l -> out_left, l2r -> out_right ----
    attn_kernel<<<agrid, 256>>>(Qb, Kb, d_l, x_right, x_left,  out_left,  0);
    attn_kernel<<<agrid, 256>>>(Kb, Qb, d_r, x_left,  x_right, out_right, 1);
}